// round 14
// baseline (speedup 1.0000x reference)
#include <cuda_runtime.h>
#include <cooperative_groups.h>
#include <math.h>
#include <stdint.h>

namespace cg = cooperative_groups;

#define T_STEPS 512
#define BATCH   256
#define HIDDEN  256
#define G4      1024
#define TB      (T_STEPS * BATCH)   // 131072

// ---- packed f32x2 helpers ---------------------------------------------------
#define FMA2(d, a, b) \
    asm("fma.rn.f32x2 %0, %1, %2, %0;" : "+l"(d) : "l"(a), "l"(b))
#define ADD2(d, a) \
    asm("add.rn.f32x2 %0, %0, %1;" : "+l"(d) : "l"(a))
#define PACK2(p, x, y) \
    asm("mov.b64 %0, {%1, %2};" : "=l"(p) : "f"(x), "f"(y))
#define UNPACK2(x, y, p) \
    asm("mov.b64 {%0, %1}, %2;" : "=f"(x), "=f"(y) : "l"(p))

__device__ __forceinline__ float fsig(float x) {
    return __fdividef(1.f, 1.f + __expf(-x));
}
__device__ __forceinline__ float ftanh(float x) {
    x = fminf(fmaxf(x, -15.f), 15.f);
    const float e = __expf(-2.f * x);
    return __fdividef(1.f - e, 1.f + e);
}

__device__ __forceinline__ void cp16(void* dst, const void* src) {
    unsigned s = (unsigned)__cvta_generic_to_shared(dst);
    asm volatile("cp.async.cg.shared.global [%0], [%1], 16;" :: "r"(s), "l"(src));
}
__device__ __forceinline__ void cp_commit() {
    asm volatile("cp.async.commit_group;");
}
__device__ __forceinline__ void cp_wait_all() {
    asm volatile("cp.async.wait_group 0;");
}

// ---- mbarrier helpers (full/empty ring across the 8-CTA cluster) -----------
__device__ __forceinline__ void mbar_init(unsigned a, unsigned cnt) {
    asm volatile("mbarrier.init.shared.b64 [%0], %1;" :: "r"(a), "r"(cnt) : "memory");
}
// arrive (release, cluster scope) on the mbar at the same SMEM offset in CTA `rank`
__device__ __forceinline__ void mbar_arrive_remote(unsigned a, unsigned rank) {
    asm volatile(
        "{\n\t.reg .b32 r;\n\t"
        "mapa.shared::cluster.u32 r, %0, %1;\n\t"
        "mbarrier.arrive.release.cluster.shared::cluster.b64 _, [r];\n\t}"
        :: "r"(a), "r"(rank) : "memory");
}
__device__ __forceinline__ void mbar_wait(unsigned a, unsigned parity) {
    unsigned done;
    asm volatile(
        "{\n\t.reg .pred p;\n\t"
        "mbarrier.try_wait.parity.acquire.cluster.shared::cta.b64 p, [%1], %2;\n\t"
        "selp.b32 %0, 1, 0, p;\n\t}"
        : "=r"(done) : "r"(a), "r"(parity) : "memory");
    if (!done) {
        asm volatile(
            "{\n\t.reg .pred p;\n\t"
            "WL_%=:\n\t"
            "mbarrier.try_wait.parity.acquire.cluster.shared::cta.b64 p, [%0], %1, 0x989680;\n\t"
            "@p bra.uni WD_%=;\n\t"
            "bra.uni WL_%=;\n\t"
            "WD_%=:\n\t}"
            :: "r"(a), "r"(parity) : "memory");
    }
}

// ---------------- scratch (device globals; no allocations allowed) ----------
__device__ float g_embed[(size_t)TB * HIDDEN];   // 134 MB
__device__ float g_xin  [(size_t)TB * G4];       // 536 MB
__device__ float g_hs   [(size_t)TB * HIDDEN];   // 134 MB
__device__ float g_a1   [(size_t)TB * 128];      //  67 MB
__device__ float g_a2   [(size_t)TB * 128];      //  67 MB

// ---------------------------------------------------------------------------
// Scalar-FFMA tiled SGEMM, BK=16, register double-buffered global loads.
// (R12 config — at the LDS-wavefront ceiling for this tiling. FROZEN.)
// ---------------------------------------------------------------------------
template<int EPI>
__global__ __launch_bounds__(256, 2)
void sgemm128(const float* __restrict__ A, const float* __restrict__ B,
              const float* __restrict__ bias, float* __restrict__ C,
              int M, int N, int K)
{
    __shared__ float As[16][128];
    __shared__ float Bs[16][128];

    const int tid = threadIdx.x;
    const int bm  = blockIdx.y;
    const int bn  = blockIdx.x;

    const int aRow = tid >> 1;
    const int aCol = (tid & 1) * 4;
    const int bRow = tid >> 5;
    const int bCol = (tid & 31) * 4;
    const int tr   = tid >> 4;
    const int tc   = tid & 15;

    const float* Ag = A + (size_t)(bm * 128 + aRow) * K + aCol;
    const float* Bg = B + (size_t)bRow * N + (size_t)bn * 128 + bCol;

    float acc[8][8];
    #pragma unroll
    for (int i = 0; i < 8; i++)
        #pragma unroll
        for (int j = 0; j < 8; j++) acc[i][j] = 0.f;

    float4 a0 = *reinterpret_cast<const float4*>(Ag);
    float4 a1 = *reinterpret_cast<const float4*>(Ag + 8);
    float4 b0 = *reinterpret_cast<const float4*>(Bg);
    float4 b1 = *reinterpret_cast<const float4*>(Bg + (size_t)8 * N);

    for (int k0 = 0; k0 < K; k0 += 16) {
        __syncthreads();
        As[aCol + 0][aRow] = a0.x;
        As[aCol + 1][aRow] = a0.y;
        As[aCol + 2][aRow] = a0.z;
        As[aCol + 3][aRow] = a0.w;
        As[aCol + 8][aRow] = a1.x;
        As[aCol + 9][aRow] = a1.y;
        As[aCol + 10][aRow] = a1.z;
        As[aCol + 11][aRow] = a1.w;
        *reinterpret_cast<float4*>(&Bs[bRow][bCol])     = b0;
        *reinterpret_cast<float4*>(&Bs[bRow + 8][bCol]) = b1;
        __syncthreads();

        const int k1 = (k0 + 16 < K) ? (k0 + 16) : k0;
        a0 = *reinterpret_cast<const float4*>(Ag + k1);
        a1 = *reinterpret_cast<const float4*>(Ag + k1 + 8);
        b0 = *reinterpret_cast<const float4*>(Bg + (size_t)k1 * N);
        b1 = *reinterpret_cast<const float4*>(Bg + (size_t)(k1 + 8) * N);

        #pragma unroll
        for (int k = 0; k < 16; k++) {
            float ra[8], rb[8];
            *reinterpret_cast<float4*>(&ra[0]) = *reinterpret_cast<const float4*>(&As[k][tr * 8]);
            *reinterpret_cast<float4*>(&ra[4]) = *reinterpret_cast<const float4*>(&As[k][tr * 8 + 4]);
            *reinterpret_cast<float4*>(&rb[0]) = *reinterpret_cast<const float4*>(&Bs[k][tc * 8]);
            *reinterpret_cast<float4*>(&rb[4]) = *reinterpret_cast<const float4*>(&Bs[k][tc * 8 + 4]);
            #pragma unroll
            for (int i = 0; i < 8; i++)
                #pragma unroll
                for (int j = 0; j < 8; j++)
                    acc[i][j] += ra[i] * rb[j];
        }
    }

    #pragma unroll
    for (int i = 0; i < 8; i++) {
        const size_t row = (size_t)bm * 128 + tr * 8 + i;
        #pragma unroll
        for (int j4 = 0; j4 < 8; j4 += 4) {
            const int col = bn * 128 + tc * 8 + j4;
            float v[4];
            #pragma unroll
            for (int j = 0; j < 4; j++) {
                float t = acc[i][j4 + j] + bias[col + j];
                if (EPI == 1) t = fmaxf(t, 0.f);
                if (EPI == 2) t = ftanh(t);
                v[j] = t;
            }
            *reinterpret_cast<float4*>(&C[row * N + col]) =
                make_float4(v[0], v[1], v[2], v[3]);
        }
    }
}

// ---------------------------------------------------------------------------
// LSTM scan — R13 structure with per-step cluster.sync REPLACED by a
// full/empty mbarrier ring (depth-1 producer/consumer pipeline):
//   full  (count 8): h(t+1) slices from all 8 CTAs have landed locally
//   empty (count 8): all 8 CTAs finished reading the buffer we overwrite
// Each CTA may run up to one step ahead of its slowest peer — skew averages
// instead of max-ing, and the per-step CCTL.IVALL L1 flush disappears.
// ---------------------------------------------------------------------------
__global__ void __cluster_dims__(8, 1, 1) __launch_bounds__(256, 1)
lstm_scan(const unsigned int* __restrict__ dones,
          const float* __restrict__ h0_c, const float* __restrict__ h0_h,
          const float* __restrict__ Wh,
          float* __restrict__ out_cfin, float* __restrict__ out_hfin)
{
    extern __shared__ float sm[];
    float* hT0 = sm;                              // 5120 ([256][20], 16 used)
    float* hT1 = sm + 5120;                       // 5120
    unsigned long long* zp =
        (unsigned long long*)(sm + 10240);        // 4096 ULL ([4kq][8p][128q])
    float* xb0  = sm + 18432;                     // 2048 ([16 b][128 q])
    float* xb1  = sm + 20480;                     // 2048
    float* c_sm = sm + 22528;                     // 512  ([16][32])
    int*   flg  = (int*)(sm + 23040);             // 16
    unsigned* dn_sm = (unsigned*)(sm + 23056);    // 8192 ([512 t][16 b])
    unsigned long long* mbars =
        (unsigned long long*)(sm + 31248);        // [0]=full, [1]=empty
    // total 31252 floats = 125008 B

    cg::cluster_group cluster = cg::this_cluster();
    const int rank = blockIdx.x & 7;
    const int B0   = (blockIdx.x >> 3) * 16;
    const int tid  = threadIdx.x;
    const int w    = tid >> 5;
    const int l    = tid & 31;
    const int ch   = w >> 2;            // column half
    const int kq   = w & 3;             // k quarter
    const int k0   = kq * 64;
    const int q0   = ch * 64 + l * 2;
    const int gc0  = ((q0 >> 5) << 8) + (rank << 5) + (q0 & 31);

    const unsigned mb_full  = (unsigned)__cvta_generic_to_shared(&mbars[0]);
    const unsigned mb_empty = (unsigned)__cvta_generic_to_shared(&mbars[1]);

    // ---- Wh slice into registers (once) ------------------------------------
    float wreg[64][2];
    #pragma unroll
    for (int kk = 0; kk < 64; kk++) {
        const float2 wv = *reinterpret_cast<const float2*>(
            Wh + ((size_t)(k0 + kk) << 10) + gc0);
        wreg[kk][0] = wv.x;
        wreg[kk][1] = wv.y;
    }

    // ---- preload ALL dones for this cluster's 16 batch rows ----------------
    for (int idx = tid; idx < 8192; idx += 256)
        dn_sm[idx] = dones[(idx >> 4) * BATCH + B0 + (idx & 15)];

    if (tid == 0) {
        mbar_init(mb_full, 8);
        mbar_init(mb_empty, 8);
    }
    __syncthreads();

    // ---- init h/c with dones[0] mask ---------------------------------------
    for (int idx = tid; idx < 4096; idx += 256) {
        const int k = idx >> 4, b = idx & 15;
        hT0[k * 20 + b] = (dn_sm[b] != 0u) ? 0.f
                                           : h0_h[(size_t)(B0 + b) * 256 + k];
    }
    for (int idx = tid; idx < 512; idx += 256) {
        const int b = idx >> 5, jj = idx & 31;
        c_sm[idx] = (dn_sm[b] != 0u)
                        ? 0.f
                        : h0_c[(size_t)(B0 + b) * 256 + (rank << 5) + jj];
    }

    // ---- prefill xin(t=0) ---------------------------------------------------
    #pragma unroll
    for (int o = tid; o < 512; o += 256) {
        const int row = o >> 5;
        const int c   = o & 31;
        const int g   = c >> 3;
        const int q   = (c & 7) * 4;
        cp16(&xb0[row * 128 + g * 32 + q],
             &g_xin[((size_t)B0 + row) * G4 + g * 256 + (rank << 5) + q]);
    }
    cp_commit();
    cp_wait_all();
    __syncthreads();
    cluster.sync();   // mbar init + initial state visible cluster-wide

    int fp = 0, ep = 0;   // full/empty phase parities

    for (int t = 0; t < T_STEPS; t++) {
        float* hTc  = (t & 1) ? hT1 : hT0;
        float* hTn  = (t & 1) ? hT0 : hT1;
        const float* xcur = (t & 1) ? xb1 : xb0;
        float*       xnxt = (t & 1) ? xb0 : xb1;

        // next step's reset mask, from SMEM
        unsigned fdone = 0u;
        if (tid < 16 && t + 1 < T_STEPS)
            fdone = dn_sm[(t + 1) * 16 + tid];

        // stage xin(t+1)
        {
            const int tn = (t + 1 < T_STEPS) ? t + 1 : t;
            #pragma unroll
            for (int o = tid; o < 512; o += 256) {
                const int row = o >> 5;
                const int c   = o & 31;
                const int g   = c >> 3;
                const int q   = (c & 7) * 4;
                cp16(&xnxt[row * 128 + g * 32 + q],
                     &g_xin[((size_t)tn * BATCH + B0 + row) * G4 + g * 256 + (rank << 5) + q]);
            }
            cp_commit();
        }

        // ---- wait until h(t) slices from all 8 CTAs have landed -------------
        if (t > 0) { mbar_wait(mb_full, (unsigned)fp); fp ^= 1; }

        // ---- partial z over this warp's k-quarter (Wh in registers) --------
        unsigned long long acc[8][2];
        #pragma unroll
        for (int p = 0; p < 8; p++) { acc[p][0] = 0ULL; acc[p][1] = 0ULL; }
        {
            const float* hp = hTc + k0 * 20;
            #pragma unroll
            for (int kk = 0; kk < 64; kk++) {
                const ulonglong2 hA = *reinterpret_cast<const ulonglong2*>(hp + kk * 20);
                const ulonglong2 hB = *reinterpret_cast<const ulonglong2*>(hp + kk * 20 + 4);
                const ulonglong2 hC = *reinterpret_cast<const ulonglong2*>(hp + kk * 20 + 8);
                const ulonglong2 hD = *reinterpret_cast<const ulonglong2*>(hp + kk * 20 + 12);
                unsigned long long w0, w1;
                PACK2(w0, wreg[kk][0], wreg[kk][0]);
                PACK2(w1, wreg[kk][1], wreg[kk][1]);
                FMA2(acc[0][0], hA.x, w0); FMA2(acc[0][1], hA.x, w1);
                FMA2(acc[1][0], hA.y, w0); FMA2(acc[1][1], hA.y, w1);
                FMA2(acc[2][0], hB.x, w0); FMA2(acc[2][1], hB.x, w1);
                FMA2(acc[3][0], hB.y, w0); FMA2(acc[3][1], hB.y, w1);
                FMA2(acc[4][0], hC.x, w0); FMA2(acc[4][1], hC.x, w1);
                FMA2(acc[5][0], hC.y, w0); FMA2(acc[5][1], hC.y, w1);
                FMA2(acc[6][0], hD.x, w0); FMA2(acc[6][1], hD.x, w1);
                FMA2(acc[7][0], hD.y, w0); FMA2(acc[7][1], hD.y, w1);
            }
        }
        #pragma unroll
        for (int p = 0; p < 8; p++) {
            ulonglong2 v; v.x = acc[p][0]; v.y = acc[p][1];
            *reinterpret_cast<ulonglong2*>(&zp[(kq * 8 + p) * 128 + q0]) = v;
        }
        if (tid < 16) flg[tid] = (fdone != 0u);
        cp_wait_all();         // own xin(t+1) chunks done (published by the bar)
        __syncthreads();       // zp + flg + xnxt visible CTA-wide

        // hTc fully consumed -> tell every CTA its next-next overwrite is safe
        if (tid < 8) mbar_arrive_remote(mb_empty, (unsigned)tid);

        // ---- reduce 4 k-partials + xin, gates, state ------------------------
        {
            const int bp   = tid >> 5;
            const int jj   = tid & 31;
            const int kcol = (rank << 5) + jj;
            float zi[2], zf[2], zg[2], zo[2];
            #pragma unroll
            for (int g = 0; g < 4; g++) {
                const int q = g * 32 + jj;
                unsigned long long s = zp[(0 * 8 + bp) * 128 + q];
                ADD2(s, zp[(1 * 8 + bp) * 128 + q]);
                ADD2(s, zp[(2 * 8 + bp) * 128 + q]);
                ADD2(s, zp[(3 * 8 + bp) * 128 + q]);
                unsigned long long xp;
                PACK2(xp, xcur[(2 * bp) * 128 + q], xcur[(2 * bp + 1) * 128 + q]);
                ADD2(s, xp);
                float a, b;
                UNPACK2(a, b, s);
                if (g == 0) { zi[0] = a; zi[1] = b; }
                else if (g == 1) { zf[0] = a; zf[1] = b; }
                else if (g == 2) { zg[0] = a; zg[1] = b; }
                else             { zo[0] = a; zo[1] = b; }
            }
            float cn_s[2], hn_s[2], hm[2];
            #pragma unroll
            for (int r = 0; r < 2; r++) {
                const int b = 2 * bp + r;
                const float co = c_sm[(b << 5) + jj];
                const float cn = fsig(zf[r]) * co + fsig(zi[r]) * ftanh(zg[r]);
                const float hn = fsig(zo[r]) * ftanh(cn);
                const bool  dn = (flg[b] != 0);
                c_sm[(b << 5) + jj] = dn ? 0.f : cn;
                hm[r]   = dn ? 0.f : hn;
                cn_s[r] = cn;
                hn_s[r] = hn;
            }

            if (t + 1 < T_STEPS) {
                // wait until every CTA finished reading the buffer we overwrite
                mbar_wait(mb_empty, (unsigned)ep); ep ^= 1;
                unsigned long long hp2;
                PACK2(hp2, hm[0], hm[1]);
                #pragma unroll
                for (int p = 0; p < 8; p++) {
                    float* dst = (float*)cluster.map_shared_rank(hTn, p);
                    *reinterpret_cast<unsigned long long*>(dst + kcol * 20 + 2 * bp) = hp2;
                }
            }
            __syncthreads();   // all pushes issued (bar drains STS); zp reads done
            if (t + 1 < T_STEPS && tid < 8)
                mbar_arrive_remote(mb_full, (unsigned)tid);

            g_hs[((size_t)t * BATCH + B0 + 2 * bp) * 256 + kcol]     = hn_s[0];
            g_hs[((size_t)t * BATCH + B0 + 2 * bp + 1) * 256 + kcol] = hn_s[1];
            if (t == T_STEPS - 1) {
                out_cfin[(size_t)(B0 + 2 * bp) * 256 + kcol]     = cn_s[0];
                out_cfin[(size_t)(B0 + 2 * bp + 1) * 256 + kcol] = cn_s[1];
                out_hfin[(size_t)(B0 + 2 * bp) * 256 + kcol]     = hn_s[0];
                out_hfin[(size_t)(B0 + 2 * bp + 1) * 256 + kcol] = hn_s[1];
            }
        }
    }
    cluster.sync();   // no CTA exits while peers' remote ops may be in flight
}

// ---------------------------------------------------------------------------
// logits = a2 @ Wa3 + ba3   (Wa3: [128,16])
// ---------------------------------------------------------------------------
__global__ __launch_bounds__(256)
void logits_kernel(const float* __restrict__ W3, const float* __restrict__ b3,
                   float* __restrict__ out)
{
    __shared__ float w3[128 * 16];
    __shared__ float rows[16 * 128];
    __shared__ float b3s[16];
    const int tid  = threadIdx.x;
    const int row0 = blockIdx.x * 16;
    for (int idx = tid; idx < 2048; idx += 256) w3[idx] = W3[idx];
    for (int idx = tid; idx < 2048; idx += 256)
        rows[idx] = g_a2[(size_t)row0 * 128 + idx];
    if (tid < 16) b3s[tid] = b3[tid];
    __syncthreads();
    const int r = tid >> 4, o = tid & 15;
    float acc = b3s[o];
    #pragma unroll 8
    for (int k = 0; k < 128; k++) acc += rows[r * 128 + k] * w3[k * 16 + o];
    out[(size_t)(row0 + r) * 16 + o] = acc;
}

// ---------------------------------------------------------------------------
// value = v2 @ Wc3 + bc3    (Wc3: [128,1]) — one warp per row
// ---------------------------------------------------------------------------
__global__ __launch_bounds__(256)
void value_kernel(const float* __restrict__ Wc3, const float* __restrict__ bc3,
                  float* __restrict__ out)
{
    __shared__ float wc[128];
    const int tid = threadIdx.x;
    if (tid < 128) wc[tid] = Wc3[tid];
    __syncthreads();
    const int warp = tid >> 5, lane = tid & 31;
    const size_t row = (size_t)blockIdx.x * 8 + warp;
    const float4 v  = *reinterpret_cast<const float4*>(&g_a2[row * 128 + lane * 4]);
    const float4 wv = *reinterpret_cast<const float4*>(&wc[lane * 4]);
    float p = v.x * wv.x + v.y * wv.y + v.z * wv.z + v.w * wv.w;
    #pragma unroll
    for (int off = 16; off; off >>= 1) p += __shfl_down_sync(0xffffffffu, p, off);
    if (lane == 0) out[row] = p + bc3[0];
}

// ---------------------------------------------------------------------------
extern "C" void kernel_launch(void* const* d_in, const int* in_sizes, int n_in,
                              void* d_out, int out_size)
{
    (void)in_sizes; (void)n_in; (void)out_size;

    const float*        x       = (const float*)d_in[0];
    const unsigned int* dones   = (const unsigned int*)d_in[1];
    const float*        h0_c    = (const float*)d_in[2];
    const float*        h0_h    = (const float*)d_in[3];
    const float*        W_embed = (const float*)d_in[4];
    const float*        b_embed = (const float*)d_in[5];
    const float*        Wi      = (const float*)d_in[6];
    const float*        Wh      = (const float*)d_in[7];
    const float*        b_lstm  = (const float*)d_in[8];
    const float*        Wa1     = (const float*)d_in[9];
    const float*        ba1     = (const float*)d_in[10];
    const float*        Wa2     = (const float*)d_in[11];
    const float*        ba2     = (const float*)d_in[12];
    const float*        Wa3     = (const float*)d_in[13];
    const float*        ba3     = (const float*)d_in[14];
    const float*        Wc1     = (const float*)d_in[15];
    const float*        bc1     = (const float*)d_in[16];
    const float*        Wc2     = (const float*)d_in[17];
    const float*        bc2     = (const float*)d_in[18];
    const float*        Wc3     = (const float*)d_in[19];
    const float*        bc3     = (const float*)d_in[20];

    float* out        = (float*)d_out;
    float* out_cfin   = out;                 // 256*256
    float* out_hfin   = out + 65536;         // 256*256
    float* out_logits = out + 131072;        // 512*256*16
    float* out_value  = out + 2228224;       // 512*256

    float *p_embed, *p_xin, *p_hs, *p_a1, *p_a2;
    cudaGetSymbolAddress((void**)&p_embed, g_embed);
    cudaGetSymbolAddress((void**)&p_xin,   g_xin);
    cudaGetSymbolAddress((void**)&p_hs,    g_hs);
    cudaGetSymbolAddress((void**)&p_a1,    g_a1);
    cudaGetSymbolAddress((void**)&p_a2,    g_a2);

    static const size_t SCAN_SMEM = 125008;   // 31252 floats
    cudaFuncSetAttribute(lstm_scan, cudaFuncAttributeMaxDynamicSharedMemorySize,
                         (int)SCAN_SMEM);

    const size_t halfM = (size_t)65536;
    // ncu captures launch #4 -> scan stays there.
    // 1) embed = relu(x @ W_embed + b_embed)
    sgemm128<1><<<dim3(2, 1024), 256>>>(x, W_embed, b_embed, p_embed, TB, 256, 256);
    // 2-3) xin = embed @ Wi + b_lstm
    sgemm128<0><<<dim3(8, 512), 256>>>(p_embed, Wi, b_lstm, p_xin, TB, 1024, 256);
    sgemm128<0><<<dim3(8, 512), 256>>>(p_embed + halfM * 256, Wi, b_lstm,
                                       p_xin + halfM * 1024, TB, 1024, 256);
    // 4) sequential LSTM scan  <-- profiled launch
    lstm_scan<<<128, 256, SCAN_SMEM>>>(dones, h0_c, h0_h, Wh, out_cfin, out_hfin);
    // 5+) heads
    sgemm128<2><<<dim3(1, 1024), 256>>>(p_hs, Wa1, ba1, p_a1, TB, 128, 256);
    sgemm128<2><<<dim3(1, 1024), 256>>>(p_a1, Wa2, ba2, p_a2, TB, 128, 128);
    logits_kernel<<<8192, 256>>>(Wa3, ba3, out_logits);
    sgemm128<2><<<dim3(1, 1024), 256>>>(p_hs, Wc1, bc1, p_a1, TB, 128, 256);
    sgemm128<2><<<dim3(1, 1024), 256>>>(p_a1, Wc2, bc2, p_a2, TB, 128, 128);
    value_kernel<<<16384, 256>>>(Wc3, bc3, out_value);
}

// round 15
// speedup vs baseline: 1.0148x; 1.0148x over previous
#include <cuda_runtime.h>
#include <cooperative_groups.h>
#include <math.h>
#include <stdint.h>

namespace cg = cooperative_groups;

#define T_STEPS 512
#define BATCH   256
#define HIDDEN  256
#define G4      1024
#define TB      (T_STEPS * BATCH)   // 131072

// ---- packed f32x2 helpers ---------------------------------------------------
#define FMA2(d, a, b) \
    asm("fma.rn.f32x2 %0, %1, %2, %0;" : "+l"(d) : "l"(a), "l"(b))
#define ADD2(d, a) \
    asm("add.rn.f32x2 %0, %0, %1;" : "+l"(d) : "l"(a))
#define PACK2(p, x, y) \
    asm("mov.b64 %0, {%1, %2};" : "=l"(p) : "f"(x), "f"(y))
#define UNPACK2(x, y, p) \
    asm("mov.b64 {%0, %1}, %2;" : "=f"(x), "=f"(y) : "l"(p))

__device__ __forceinline__ float fsig(float x) {
    return __fdividef(1.f, 1.f + __expf(-x));
}
__device__ __forceinline__ float ftanh(float x) {
    x = fminf(fmaxf(x, -15.f), 15.f);
    const float e = __expf(-2.f * x);
    return __fdividef(1.f - e, 1.f + e);
}

__device__ __forceinline__ void cp16(void* dst, const void* src) {
    unsigned s = (unsigned)__cvta_generic_to_shared(dst);
    asm volatile("cp.async.cg.shared.global [%0], [%1], 16;" :: "r"(s), "l"(src));
}
__device__ __forceinline__ void cp_commit() {
    asm volatile("cp.async.commit_group;");
}
__device__ __forceinline__ void cp_wait_all() {
    asm volatile("cp.async.wait_group 0;");
}

// ---------------- scratch (device globals; no allocations allowed) ----------
__device__ float g_embed[(size_t)TB * HIDDEN];   // 134 MB
__device__ float g_xin  [(size_t)TB * G4];       // 536 MB
__device__ float g_hs   [(size_t)TB * HIDDEN];   // 134 MB
__device__ float g_a1   [(size_t)TB * 128];      //  67 MB
__device__ float g_a2   [(size_t)TB * 128];      //  67 MB

// ---------------------------------------------------------------------------
// Scalar-FFMA tiled SGEMM, BK=16, register double-buffered global loads.
// (R12 config — at the LDS-wavefront ceiling for this tiling. FROZEN.)
// ---------------------------------------------------------------------------
template<int EPI>
__global__ __launch_bounds__(256, 2)
void sgemm128(const float* __restrict__ A, const float* __restrict__ B,
              const float* __restrict__ bias, float* __restrict__ C,
              int M, int N, int K)
{
    __shared__ float As[16][128];
    __shared__ float Bs[16][128];

    const int tid = threadIdx.x;
    const int bm  = blockIdx.y;
    const int bn  = blockIdx.x;

    const int aRow = tid >> 1;
    const int aCol = (tid & 1) * 4;
    const int bRow = tid >> 5;
    const int bCol = (tid & 31) * 4;
    const int tr   = tid >> 4;
    const int tc   = tid & 15;

    const float* Ag = A + (size_t)(bm * 128 + aRow) * K + aCol;
    const float* Bg = B + (size_t)bRow * N + (size_t)bn * 128 + bCol;

    float acc[8][8];
    #pragma unroll
    for (int i = 0; i < 8; i++)
        #pragma unroll
        for (int j = 0; j < 8; j++) acc[i][j] = 0.f;

    float4 a0 = *reinterpret_cast<const float4*>(Ag);
    float4 a1 = *reinterpret_cast<const float4*>(Ag + 8);
    float4 b0 = *reinterpret_cast<const float4*>(Bg);
    float4 b1 = *reinterpret_cast<const float4*>(Bg + (size_t)8 * N);

    for (int k0 = 0; k0 < K; k0 += 16) {
        __syncthreads();
        As[aCol + 0][aRow] = a0.x;
        As[aCol + 1][aRow] = a0.y;
        As[aCol + 2][aRow] = a0.z;
        As[aCol + 3][aRow] = a0.w;
        As[aCol + 8][aRow] = a1.x;
        As[aCol + 9][aRow] = a1.y;
        As[aCol + 10][aRow] = a1.z;
        As[aCol + 11][aRow] = a1.w;
        *reinterpret_cast<float4*>(&Bs[bRow][bCol])     = b0;
        *reinterpret_cast<float4*>(&Bs[bRow + 8][bCol]) = b1;
        __syncthreads();

        const int k1 = (k0 + 16 < K) ? (k0 + 16) : k0;
        a0 = *reinterpret_cast<const float4*>(Ag + k1);
        a1 = *reinterpret_cast<const float4*>(Ag + k1 + 8);
        b0 = *reinterpret_cast<const float4*>(Bg + (size_t)k1 * N);
        b1 = *reinterpret_cast<const float4*>(Bg + (size_t)(k1 + 8) * N);

        #pragma unroll
        for (int k = 0; k < 16; k++) {
            float ra[8], rb[8];
            *reinterpret_cast<float4*>(&ra[0]) = *reinterpret_cast<const float4*>(&As[k][tr * 8]);
            *reinterpret_cast<float4*>(&ra[4]) = *reinterpret_cast<const float4*>(&As[k][tr * 8 + 4]);
            *reinterpret_cast<float4*>(&rb[0]) = *reinterpret_cast<const float4*>(&Bs[k][tc * 8]);
            *reinterpret_cast<float4*>(&rb[4]) = *reinterpret_cast<const float4*>(&Bs[k][tc * 8 + 4]);
            #pragma unroll
            for (int i = 0; i < 8; i++)
                #pragma unroll
                for (int j = 0; j < 8; j++)
                    acc[i][j] += ra[i] * rb[j];
        }
    }

    #pragma unroll
    for (int i = 0; i < 8; i++) {
        const size_t row = (size_t)bm * 128 + tr * 8 + i;
        #pragma unroll
        for (int j4 = 0; j4 < 8; j4 += 4) {
            const int col = bn * 128 + tc * 8 + j4;
            float v[4];
            #pragma unroll
            for (int j = 0; j < 4; j++) {
                float t = acc[i][j4 + j] + bias[col + j];
                if (EPI == 1) t = fmaxf(t, 0.f);
                if (EPI == 2) t = ftanh(t);
                v[j] = t;
            }
            *reinterpret_cast<float4*>(&C[row * N + col]) =
                make_float4(v[0], v[1], v[2], v[3]);
        }
    }
}

// ---------------------------------------------------------------------------
// LSTM scan — R13 structure (best: 7484) + R15 dependency-chain fixes:
//   * GEMM inner loop software-pipelines the 4 h LDS.128s (prefetch k+1
//     during k's FMA block) so the 29-cyc LDS latency hides under compute
//   * reduce phase issues all 16 zp + 4 xin loads before the ADD2 chains
//   * flg staging removed — gates read dn_sm directly
// Sync scheme identical to R13 (cluster arrive/wait split with the global
// stores inside the window).
// ---------------------------------------------------------------------------
__global__ void __cluster_dims__(8, 1, 1) __launch_bounds__(256, 1)
lstm_scan(const unsigned int* __restrict__ dones,
          const float* __restrict__ h0_c, const float* __restrict__ h0_h,
          const float* __restrict__ Wh,
          float* __restrict__ out_cfin, float* __restrict__ out_hfin)
{
    extern __shared__ float sm[];
    float* hT0 = sm;                              // 5120 ([256][20], 16 used)
    float* hT1 = sm + 5120;                       // 5120
    unsigned long long* zp =
        (unsigned long long*)(sm + 10240);        // 4096 ULL ([4kq][8p][128q])
    float* xb0  = sm + 18432;                     // 2048 ([16 b][128 q])
    float* xb1  = sm + 20480;                     // 2048
    float* c_sm = sm + 22528;                     // 512  ([16][32])
    unsigned* dn_sm = (unsigned*)(sm + 23056);    // 8192 ([512 t][16 b])
    // total 31248 floats = 124992 B

    cg::cluster_group cluster = cg::this_cluster();
    const int rank = blockIdx.x & 7;
    const int B0   = (blockIdx.x >> 3) * 16;
    const int tid  = threadIdx.x;
    const int w    = tid >> 5;
    const int l    = tid & 31;
    const int ch   = w >> 2;            // column half
    const int kq   = w & 3;             // k quarter
    const int k0   = kq * 64;
    const int q0   = ch * 64 + l * 2;
    const int gc0  = ((q0 >> 5) << 8) + (rank << 5) + (q0 & 31);

    // ---- Wh slice into registers (once) ------------------------------------
    float wreg[64][2];
    #pragma unroll
    for (int kk = 0; kk < 64; kk++) {
        const float2 wv = *reinterpret_cast<const float2*>(
            Wh + ((size_t)(k0 + kk) << 10) + gc0);
        wreg[kk][0] = wv.x;
        wreg[kk][1] = wv.y;
    }

    // ---- preload ALL dones for this cluster's 16 batch rows ----------------
    for (int idx = tid; idx < 8192; idx += 256)
        dn_sm[idx] = dones[(idx >> 4) * BATCH + B0 + (idx & 15)];
    __syncthreads();

    // ---- init h/c with dones[0] mask ---------------------------------------
    for (int idx = tid; idx < 4096; idx += 256) {
        const int k = idx >> 4, b = idx & 15;
        hT0[k * 20 + b] = (dn_sm[b] != 0u) ? 0.f
                                           : h0_h[(size_t)(B0 + b) * 256 + k];
    }
    for (int idx = tid; idx < 512; idx += 256) {
        const int b = idx >> 5, jj = idx & 31;
        c_sm[idx] = (dn_sm[b] != 0u)
                        ? 0.f
                        : h0_c[(size_t)(B0 + b) * 256 + (rank << 5) + jj];
    }

    // ---- prefill xin(t=0) ---------------------------------------------------
    #pragma unroll
    for (int o = tid; o < 512; o += 256) {
        const int row = o >> 5;
        const int c   = o & 31;
        const int g   = c >> 3;
        const int q   = (c & 7) * 4;
        cp16(&xb0[row * 128 + g * 32 + q],
             &g_xin[((size_t)B0 + row) * G4 + g * 256 + (rank << 5) + q]);
    }
    cp_commit();
    cp_wait_all();
    __syncthreads();
    cluster.sync();

    for (int t = 0; t < T_STEPS; t++) {
        float* hTc  = (t & 1) ? hT1 : hT0;
        float* hTn  = (t & 1) ? hT0 : hT1;
        const float* xcur = (t & 1) ? xb1 : xb0;
        float*       xnxt = (t & 1) ? xb0 : xb1;

        // stage xin(t+1)
        {
            const int tn = (t + 1 < T_STEPS) ? t + 1 : t;
            #pragma unroll
            for (int o = tid; o < 512; o += 256) {
                const int row = o >> 5;
                const int c   = o & 31;
                const int g   = c >> 3;
                const int q   = (c & 7) * 4;
                cp16(&xnxt[row * 128 + g * 32 + q],
                     &g_xin[((size_t)tn * BATCH + B0 + row) * G4 + g * 256 + (rank << 5) + q]);
            }
            cp_commit();
        }

        // ---- partial z over this warp's k-quarter (Wh in registers) --------
        // h LDS.128s software-pipelined: k+1's loads issue before k's FMAs.
        unsigned long long acc[8][2];
        #pragma unroll
        for (int p = 0; p < 8; p++) { acc[p][0] = 0ULL; acc[p][1] = 0ULL; }
        {
            const float* hp = hTc + k0 * 20;
            ulonglong2 nA = *reinterpret_cast<const ulonglong2*>(hp);
            ulonglong2 nB = *reinterpret_cast<const ulonglong2*>(hp + 4);
            ulonglong2 nC = *reinterpret_cast<const ulonglong2*>(hp + 8);
            ulonglong2 nD = *reinterpret_cast<const ulonglong2*>(hp + 12);
            #pragma unroll
            for (int kk = 0; kk < 64; kk++) {
                const ulonglong2 hA = nA, hB = nB, hC = nC, hD = nD;
                if (kk < 63) {
                    const float* np = hp + (kk + 1) * 20;
                    nA = *reinterpret_cast<const ulonglong2*>(np);
                    nB = *reinterpret_cast<const ulonglong2*>(np + 4);
                    nC = *reinterpret_cast<const ulonglong2*>(np + 8);
                    nD = *reinterpret_cast<const ulonglong2*>(np + 12);
                }
                unsigned long long w0, w1;
                PACK2(w0, wreg[kk][0], wreg[kk][0]);
                PACK2(w1, wreg[kk][1], wreg[kk][1]);
                FMA2(acc[0][0], hA.x, w0); FMA2(acc[0][1], hA.x, w1);
                FMA2(acc[1][0], hA.y, w0); FMA2(acc[1][1], hA.y, w1);
                FMA2(acc[2][0], hB.x, w0); FMA2(acc[2][1], hB.x, w1);
                FMA2(acc[3][0], hB.y, w0); FMA2(acc[3][1], hB.y, w1);
                FMA2(acc[4][0], hC.x, w0); FMA2(acc[4][1], hC.x, w1);
                FMA2(acc[5][0], hC.y, w0); FMA2(acc[5][1], hC.y, w1);
                FMA2(acc[6][0], hD.x, w0); FMA2(acc[6][1], hD.x, w1);
                FMA2(acc[7][0], hD.y, w0); FMA2(acc[7][1], hD.y, w1);
            }
        }
        #pragma unroll
        for (int p = 0; p < 8; p++) {
            ulonglong2 v; v.x = acc[p][0]; v.y = acc[p][1];
            *reinterpret_cast<ulonglong2*>(&zp[(kq * 8 + p) * 128 + q0]) = v;
        }
        __syncthreads();

        // ---- reduce 4 k-partials + xin, gates, state, DSMEM broadcast ------
        {
            const int bp   = tid >> 5;
            const int jj   = tid & 31;
            const int kcol = (rank << 5) + jj;

            // issue ALL loads first (20 independent), then the ADD chains
            unsigned long long z0[4], z1[4], z2[4], z3[4], xp[4];
            #pragma unroll
            for (int g = 0; g < 4; g++) {
                const int q = g * 32 + jj;
                z0[g] = zp[(0 * 8 + bp) * 128 + q];
                z1[g] = zp[(1 * 8 + bp) * 128 + q];
                z2[g] = zp[(2 * 8 + bp) * 128 + q];
                z3[g] = zp[(3 * 8 + bp) * 128 + q];
                PACK2(xp[g], xcur[(2 * bp) * 128 + q], xcur[(2 * bp + 1) * 128 + q]);
            }
            float zi[2], zf[2], zg[2], zo[2];
            #pragma unroll
            for (int g = 0; g < 4; g++) {
                ADD2(z0[g], z1[g]);
                ADD2(z2[g], z3[g]);
                ADD2(z0[g], xp[g]);
                ADD2(z0[g], z2[g]);
                float a, b;
                UNPACK2(a, b, z0[g]);
                if (g == 0) { zi[0] = a; zi[1] = b; }
                else if (g == 1) { zf[0] = a; zf[1] = b; }
                else if (g == 2) { zg[0] = a; zg[1] = b; }
                else             { zo[0] = a; zo[1] = b; }
            }

            // reset mask for step t+1 read straight from SMEM (no staging)
            unsigned d0 = 0u, d1 = 0u;
            if (t + 1 < T_STEPS) {
                d0 = dn_sm[(t + 1) * 16 + 2 * bp];
                d1 = dn_sm[(t + 1) * 16 + 2 * bp + 1];
            }

            float cn_s[2], hn_s[2], hm[2];
            #pragma unroll
            for (int r = 0; r < 2; r++) {
                const int b = 2 * bp + r;
                const float co = c_sm[(b << 5) + jj];
                const float cn = fsig(zf[r]) * co + fsig(zi[r]) * ftanh(zg[r]);
                const float hn = fsig(zo[r]) * ftanh(cn);
                const bool  dn = ((r == 0 ? d0 : d1) != 0u);
                c_sm[(b << 5) + jj] = dn ? 0.f : cn;
                hm[r]   = dn ? 0.f : hn;
                cn_s[r] = cn;
                hn_s[r] = hn;
            }
            unsigned long long hp2;
            PACK2(hp2, hm[0], hm[1]);
            #pragma unroll
            for (int p = 0; p < 8; p++) {
                float* dst = (float*)cluster.map_shared_rank(hTn, p);
                *reinterpret_cast<unsigned long long*>(dst + kcol * 20 + 2 * bp) = hp2;
            }

            // arrive (release: DSMEM stores visible at peers' wait);
            // global stores live inside the arrive->wait window.
            cp_wait_all();
            asm volatile("barrier.cluster.arrive.aligned;" ::: "memory");
            g_hs[((size_t)t * BATCH + B0 + 2 * bp) * 256 + kcol]     = hn_s[0];
            g_hs[((size_t)t * BATCH + B0 + 2 * bp + 1) * 256 + kcol] = hn_s[1];
            if (t == T_STEPS - 1) {
                out_cfin[(size_t)(B0 + 2 * bp) * 256 + kcol]     = cn_s[0];
                out_cfin[(size_t)(B0 + 2 * bp + 1) * 256 + kcol] = cn_s[1];
                out_hfin[(size_t)(B0 + 2 * bp) * 256 + kcol]     = hn_s[0];
                out_hfin[(size_t)(B0 + 2 * bp + 1) * 256 + kcol] = hn_s[1];
            }
            asm volatile("barrier.cluster.wait.aligned;" ::: "memory");
        }
    }
}

// ---------------------------------------------------------------------------
// logits = a2 @ Wa3 + ba3   (Wa3: [128,16])
// ---------------------------------------------------------------------------
__global__ __launch_bounds__(256)
void logits_kernel(const float* __restrict__ W3, const float* __restrict__ b3,
                   float* __restrict__ out)
{
    __shared__ float w3[128 * 16];
    __shared__ float rows[16 * 128];
    __shared__ float b3s[16];
    const int tid  = threadIdx.x;
    const int row0 = blockIdx.x * 16;
    for (int idx = tid; idx < 2048; idx += 256) w3[idx] = W3[idx];
    for (int idx = tid; idx < 2048; idx += 256)
        rows[idx] = g_a2[(size_t)row0 * 128 + idx];
    if (tid < 16) b3s[tid] = b3[tid];
    __syncthreads();
    const int r = tid >> 4, o = tid & 15;
    float acc = b3s[o];
    #pragma unroll 8
    for (int k = 0; k < 128; k++) acc += rows[r * 128 + k] * w3[k * 16 + o];
    out[(size_t)(row0 + r) * 16 + o] = acc;
}

// ---------------------------------------------------------------------------
// value = v2 @ Wc3 + bc3    (Wc3: [128,1]) — one warp per row
// ---------------------------------------------------------------------------
__global__ __launch_bounds__(256)
void value_kernel(const float* __restrict__ Wc3, const float* __restrict__ bc3,
                  float* __restrict__ out)
{
    __shared__ float wc[128];
    const int tid = threadIdx.x;
    if (tid < 128) wc[tid] = Wc3[tid];
    __syncthreads();
    const int warp = tid >> 5, lane = tid & 31;
    const size_t row = (size_t)blockIdx.x * 8 + warp;
    const float4 v  = *reinterpret_cast<const float4*>(&g_a2[row * 128 + lane * 4]);
    const float4 wv = *reinterpret_cast<const float4*>(&wc[lane * 4]);
    float p = v.x * wv.x + v.y * wv.y + v.z * wv.z + v.w * wv.w;
    #pragma unroll
    for (int off = 16; off; off >>= 1) p += __shfl_down_sync(0xffffffffu, p, off);
    if (lane == 0) out[row] = p + bc3[0];
}

// ---------------------------------------------------------------------------
extern "C" void kernel_launch(void* const* d_in, const int* in_sizes, int n_in,
                              void* d_out, int out_size)
{
    (void)in_sizes; (void)n_in; (void)out_size;

    const float*        x       = (const float*)d_in[0];
    const unsigned int* dones   = (const unsigned int*)d_in[1];
    const float*        h0_c    = (const float*)d_in[2];
    const float*        h0_h    = (const float*)d_in[3];
    const float*        W_embed = (const float*)d_in[4];
    const float*        b_embed = (const float*)d_in[5];
    const float*        Wi      = (const float*)d_in[6];
    const float*        Wh      = (const float*)d_in[7];
    const float*        b_lstm  = (const float*)d_in[8];
    const float*        Wa1     = (const float*)d_in[9];
    const float*        ba1     = (const float*)d_in[10];
    const float*        Wa2     = (const float*)d_in[11];
    const float*        ba2     = (const float*)d_in[12];
    const float*        Wa3     = (const float*)d_in[13];
    const float*        ba3     = (const float*)d_in[14];
    const float*        Wc1     = (const float*)d_in[15];
    const float*        bc1     = (const float*)d_in[16];
    const float*        Wc2     = (const float*)d_in[17];
    const float*        bc2     = (const float*)d_in[18];
    const float*        Wc3     = (const float*)d_in[19];
    const float*        bc3     = (const float*)d_in[20];

    float* out        = (float*)d_out;
    float* out_cfin   = out;                 // 256*256
    float* out_hfin   = out + 65536;         // 256*256
    float* out_logits = out + 131072;        // 512*256*16
    float* out_value  = out + 2228224;       // 512*256

    float *p_embed, *p_xin, *p_hs, *p_a1, *p_a2;
    cudaGetSymbolAddress((void**)&p_embed, g_embed);
    cudaGetSymbolAddress((void**)&p_xin,   g_xin);
    cudaGetSymbolAddress((void**)&p_hs,    g_hs);
    cudaGetSymbolAddress((void**)&p_a1,    g_a1);
    cudaGetSymbolAddress((void**)&p_a2,    g_a2);

    static const size_t SCAN_SMEM = 124992;   // 31248 floats
    cudaFuncSetAttribute(lstm_scan, cudaFuncAttributeMaxDynamicSharedMemorySize,
                         (int)SCAN_SMEM);

    const size_t halfM = (size_t)65536;
    // ncu captures launch #4 -> scan stays there.
    // 1) embed = relu(x @ W_embed + b_embed)
    sgemm128<1><<<dim3(2, 1024), 256>>>(x, W_embed, b_embed, p_embed, TB, 256, 256);
    // 2-3) xin = embed @ Wi + b_lstm
    sgemm128<0><<<dim3(8, 512), 256>>>(p_embed, Wi, b_lstm, p_xin, TB, 1024, 256);
    sgemm128<0><<<dim3(8, 512), 256>>>(p_embed + halfM * 256, Wi, b_lstm,
                                       p_xin + halfM * 1024, TB, 1024, 256);
    // 4) sequential LSTM scan  <-- profiled launch
    lstm_scan<<<128, 256, SCAN_SMEM>>>(dones, h0_c, h0_h, Wh, out_cfin, out_hfin);
    // 5+) heads
    sgemm128<2><<<dim3(1, 1024), 256>>>(p_hs, Wa1, ba1, p_a1, TB, 128, 256);
    sgemm128<2><<<dim3(1, 1024), 256>>>(p_a1, Wa2, ba2, p_a2, TB, 128, 128);
    logits_kernel<<<8192, 256>>>(Wa3, ba3, out_logits);
    sgemm128<2><<<dim3(1, 1024), 256>>>(p_hs, Wc1, bc1, p_a1, TB, 128, 256);
    sgemm128<2><<<dim3(1, 1024), 256>>>(p_a1, Wc2, bc2, p_a2, TB, 128, 128);
    value_kernel<<<16384, 256>>>(Wc3, bc3, out_value);
}